// round 12
// baseline (speedup 1.0000x reference)
#include <cuda_runtime.h>
#include <cuda_bf16.h>

#define Bb 256
#define Tt 240
#define Cc 512
#define Kk 64
#define NCn 4
#define TB 8
#define NCHUNK 30
#define NT 1024
#define CPAD 514
#define XS 516           // x row stride (floats): t*4 offsets -> conflict-free B frags
#define AS 68            // a_s row stride
#define VS 513           // vlad row stride

// smem byte offsets
#define CONV_OFF 0                 // f32 [64][514] = 131584 (vlad overlays: 64*513*4=131328)
#define XRAW_OFF 131584            // f32 [2][8][516] = 33024
#define RED_OFF  164608            // f32 [8][16][64] = 32768
#define A_OFF    197376            // f32 [8][68] = 2176
#define ASUM_OFF 199552            // f32[64]
#define KN_OFF   199808            // f32[64]
#define MISC_OFF 200064            // f32[8]
#define WRED_OFF 200096            // f32[8]
#define SMEM_TOTAL 200128

typedef unsigned long long ull;
typedef unsigned int uint;

__device__ __forceinline__ ull ffma2(ull a, ull b, ull c){ull d;asm("fma.rn.f32x2 %0,%1,%2,%3;":"=l"(d):"l"(a),"l"(b),"l"(c));return d;}
__device__ __forceinline__ float lo32(ull v){return __uint_as_float((uint)v);}
__device__ __forceinline__ float hi32(ull v){return __uint_as_float((uint)(v>>32));}
__device__ __forceinline__ void cp_async16(void* d,const void* s){uint a=(uint)__cvta_generic_to_shared(d);asm volatile("cp.async.cg.shared.global [%0],[%1],16;"::"r"(a),"l"(s));}
// pack {lo=x0, hi=x1} as bf16x2
__device__ __forceinline__ uint bfp(float x0, float x1){uint r;asm("cvt.rn.bf16x2.f32 %0,%1,%2;":"=r"(r):"f"(x1),"f"(x0));return r;}

__global__ void __launch_bounds__(NT,1)
netvlad_kernel(const float* __restrict__ gin, const float* __restrict__ candA,
               const float* __restrict__ candB, const float* __restrict__ gfcw,
               const float* __restrict__ gfcb, float* __restrict__ gout)
{
    extern __shared__ __align__(1024) char smraw[];
    float* conv_s=(float*)(smraw+CONV_OFF);
    float* red   =(float*)(smraw+RED_OFF);
    float* a_s   =(float*)(smraw+A_OFF);
    float* asum_s=(float*)(smraw+ASUM_OFF);
    float* knorm =(float*)(smraw+KN_OFF);
    float* misc  =(float*)(smraw+MISC_OFF);
    float* wred  =(float*)(smraw+WRED_OFF);
    const int tid=threadIdx.x, lane=tid&31, warp=tid>>5, b=blockIdx.x;

    if (warp==0){
        float s=fabsf(candA[lane])+fabsf(candA[lane+32])+fabsf(candA[lane+64])+fabsf(candA[lane+96]);
        #pragma unroll
        for(int o=16;o;o>>=1) s+=__shfl_xor_sync(0xffffffffu,s,o);
        if(lane==0) misc[7]=s;
    }
    if (tid<Kk){asum_s[tid]=0.f; knorm[tid]=0.f;}
    if (tid<8) wred[tid]=0.f;
    __syncthreads();
    const bool aIsConv=(misc[7]<25.6f);
    const float* gconv=aIsConv?candA:candB;
    const float* gcent=aIsConv?candB:candA;
    __syncthreads();

    for(int idx=tid;idx<Kk*Cc;idx+=NT){int k=idx>>9,c=idx&511;conv_s[k*CPAD+c]=gconv[idx];}

    const float* inb=gin+(size_t)b*(Tt*Cc);
    {   // chunk 0 -> xbuf[0]
        int row=tid>>7, col=(tid&127)<<2;
        *(float4*)((float*)(smraw+XRAW_OFF)+row*XS+col)=*(const float4*)(inb+row*Cc+col);
    }

    // MMA frag ids
    const int grp=lane>>2, tig=lane&3, t0=2*tig;
    const int kt=warp>>3, cg=warp&7;        // k-tile (16 rows), c-group (64 cols)
    const int k0=kt*16+grp;
    float acc[8][4];
    #pragma unroll
    for(int i=0;i<8;i++){acc[i][0]=0.f;acc[i][1]=0.f;acc[i][2]=0.f;acc[i][3]=0.f;}
    __syncthreads();

    for (int ch=0; ch<NCHUNK; ch++){
        float* xb=(float*)(smraw+XRAW_OFF)+(ch&1)*(TB*XS);
        if (ch+1<NCHUNK){
            int row=tid>>7, col=(tid&127)<<2;
            cp_async16((float*)(smraw+XRAW_OFF)+((ch+1)&1)*(TB*XS)+row*XS+col,
                       inb+(ch+1)*(TB*Cc)+row*Cc+col);
            asm volatile("cp.async.commit_group;");
        }
        // phase 1: normalize rows (warps 0-7)
        if (warp<8){
            float* rp=xb+warp*XS+4*lane;
            float4 q0=*(float4*)rp,q1=*(float4*)(rp+128),q2=*(float4*)(rp+256),q3=*(float4*)(rp+384);
            float ss=q0.x*q0.x+q0.y*q0.y+q0.z*q0.z+q0.w*q0.w+q1.x*q1.x+q1.y*q1.y+q1.z*q1.z+q1.w*q1.w
                    +q2.x*q2.x+q2.y*q2.y+q2.z*q2.z+q2.w*q2.w+q3.x*q3.x+q3.y*q3.y+q3.z*q3.z+q3.w*q3.w;
            #pragma unroll
            for(int o=16;o;o>>=1) ss+=__shfl_xor_sync(0xffffffffu,ss,o);
            float iv=1.0f/fmaxf(sqrtf(ss),1e-12f);
            *(float4*)rp      =make_float4(q0.x*iv,q0.y*iv,q0.z*iv,q0.w*iv);
            *(float4*)(rp+128)=make_float4(q1.x*iv,q1.y*iv,q1.z*iv,q1.w*iv);
            *(float4*)(rp+256)=make_float4(q2.x*iv,q2.y*iv,q2.z*iv,q2.w*iv);
            *(float4*)(rp+384)=make_float4(q3.x*iv,q3.y*iv,q3.z*iv,q3.w*iv);
        }
        __syncthreads();   // B1
        // phase 2: logits
        {
            const int tg=warp>>4, seg=warp&15;
            ull lacc[4][2];
            #pragma unroll
            for(int t=0;t<4;t++){lacc[t][0]=0;lacc[t][1]=0;}
            const float* wpa=conv_s+lane*CPAD+seg*32;
            const float* wpb=wpa+32*CPAD;
            const float* xp=xb+tg*4*XS+seg*32;
            #pragma unroll 4
            for(int cp=0;cp<16;cp++){
                ull wa=*(const ull*)(wpa+2*cp);
                ull wb=*(const ull*)(wpb+2*cp);
                #pragma unroll
                for(int t=0;t<4;t++){
                    ull x2=*(const ull*)(xp+t*XS+2*cp);
                    lacc[t][0]=ffma2(wa,x2,lacc[t][0]);
                    lacc[t][1]=ffma2(wb,x2,lacc[t][1]);
                }
            }
            #pragma unroll
            for(int t=0;t<4;t++){
                int tt=tg*4+t;
                red[tt*1024+seg*64+lane]   =lo32(lacc[t][0])+hi32(lacc[t][0]);
                red[tt*1024+seg*64+lane+32]=lo32(lacc[t][1])+hi32(lacc[t][1]);
            }
        }
        __syncthreads();   // B2
        // softmax (warps 0-7): a_s + asum
        if (warp<8){
            const int t=warp;
            float lg0=0.f,lg1=0.f;
            #pragma unroll
            for(int s=0;s<16;s++){lg0+=red[t*1024+s*64+lane];lg1+=red[t*1024+s*64+lane+32];}
            float m=fmaxf(lg0,lg1);
            #pragma unroll
            for(int o=16;o;o>>=1) m=fmaxf(m,__shfl_xor_sync(0xffffffffu,m,o));
            float e0=__expf(lg0-m),e1=__expf(lg1-m),s2=e0+e1;
            #pragma unroll
            for(int o=16;o;o>>=1) s2+=__shfl_xor_sync(0xffffffffu,s2,o);
            float a0=e0/s2,a1=e1/s2;
            a_s[t*AS+lane]=a0; a_s[t*AS+lane+32]=a1;
            atomicAdd(&asum_s[lane],a0); atomicAdd(&asum_s[lane+32],a1);
        }
        __syncthreads();   // B3
        // phase 3: HMMA VLAD update — 8 m16n8k8 tiles per warp
        {
            uint fa0=bfp(a_s[t0*AS+k0],   a_s[(t0+1)*AS+k0]);
            uint fa1=bfp(a_s[t0*AS+k0+8], a_s[(t0+1)*AS+k0+8]);
            const int cb=cg*64+grp;
            #pragma unroll
            for(int i=0;i<8;i++){
                int c=cb+i*8;
                uint fb=bfp(xb[t0*XS+c], xb[(t0+1)*XS+c]);
                asm("mma.sync.aligned.m16n8k8.row.col.f32.bf16.bf16.f32 "
                    "{%0,%1,%2,%3},{%4,%5},{%6},{%0,%1,%2,%3};"
                    : "+f"(acc[i][0]),"+f"(acc[i][1]),"+f"(acc[i][2]),"+f"(acc[i][3])
                    : "r"(fa0),"r"(fa1),"r"(fb));
            }
        }
        if (ch+1<NCHUNK) asm volatile("cp.async.wait_group 0;");
        __syncthreads();   // B4
    }

    // ===== epilogue =====
    float* vlad=(float*)smraw;   // overlay conv_s, stride VS
    {
        int r0=kt*16+grp, r1=r0+8;
        float a0s=asum_s[r0], a1s=asum_s[r1];
        float pk0=0.f, pk1=0.f;
        #pragma unroll
        for(int i=0;i<8;i++){
            int c=cg*64+i*8+2*tig;
            float2 c0=*(const float2*)(gcent+(size_t)r0*Cc+c);
            float2 c1=*(const float2*)(gcent+(size_t)r1*Cc+c);
            float v00=acc[i][0]-a0s*c0.x, v01=acc[i][1]-a0s*c0.y;
            float v10=acc[i][2]-a1s*c1.x, v11=acc[i][3]-a1s*c1.y;
            vlad[r0*VS+c]=v00; vlad[r0*VS+c+1]=v01;
            vlad[r1*VS+c]=v10; vlad[r1*VS+c+1]=v11;
            pk0+=v00*v00+v01*v01; pk1+=v10*v10+v11*v11;
        }
        pk0+=__shfl_xor_sync(0xffffffffu,pk0,1); pk0+=__shfl_xor_sync(0xffffffffu,pk0,2);
        pk1+=__shfl_xor_sync(0xffffffffu,pk1,1); pk1+=__shfl_xor_sync(0xffffffffu,pk1,2);
        if(tig==0){atomicAdd(&knorm[r0],pk0); atomicAdd(&knorm[r1],pk1);}
    }
    __syncthreads();
    if (warp==0){
        float c0=0.f;
        #pragma unroll
        for(int r=0;r<2;r++){float nn=knorm[lane+32*r];float iv=1.0f/fmaxf(sqrtf(nn),1e-12f);c0+=nn*iv*iv;}
        #pragma unroll
        for(int o=16;o;o>>=1) c0+=__shfl_xor_sync(0xffffffffu,c0,o);
        if(lane==0) misc[0]=1.0f/fmaxf(sqrtf(c0),1e-12f);
    }
    __syncthreads();
    {
        float invtot=misc[0];
        int k=tid>>4;
        float sc=(1.0f/fmaxf(sqrtf(knorm[k]),1e-12f))*invtot;
        int off=(tid&15)*32;
        float fo[NCn]={0.f,0.f,0.f,0.f};
        #pragma unroll 4
        for(int o=0;o<32;o++){
            int j=off+((o+lane)&31);
            float v=vlad[k*VS+j]*sc;
            #pragma unroll
            for(int n=0;n<NCn;n++) fo[n]+=v*gfcw[(size_t)n*(Kk*Cc)+k*Cc+j];
        }
        #pragma unroll
        for(int n=0;n<NCn;n++){
            float v=fo[n];
            #pragma unroll
            for(int o=16;o;o>>=1) v+=__shfl_xor_sync(0xffffffffu,v,o);
            if(lane==0) atomicAdd(&wred[n],v);
        }
    }
    __syncthreads();
    if (tid<NCn){
        float z=gfcb[tid]+wred[tid];
        gout[b*NCn+tid]=1.0f/(1.0f+__expf(-z));
    }
}

extern "C" void kernel_launch(void* const* d_in, const int* in_sizes, int n_in,
                              void* d_out, int out_size) {
    const float *gin=nullptr,*gfcw=nullptr,*gfcb=nullptr,*cand[2]={nullptr,nullptr};
    if (n_in>=5){
        int used[32]; for(int i=0;i<n_in&&i<32;i++) used[i]=0;
        int imax=-1; for(int i=0;i<n_in&&i<32;i++) if(!used[i]&&(imax<0||in_sizes[i]>in_sizes[imax])) imax=i;
        used[imax]=1; gin=(const float*)d_in[imax];
        int imin=-1; for(int i=0;i<n_in&&i<32;i++) if(!used[i]&&(imin<0||in_sizes[i]<in_sizes[imin])) imin=i;
        used[imin]=1; gfcb=(const float*)d_in[imin];
        int iw=-1; for(int i=0;i<n_in&&i<32;i++) if(!used[i]&&(iw<0||in_sizes[i]>in_sizes[iw])) iw=i;
        used[iw]=1; gfcw=(const float*)d_in[iw];
        int nc=0; for(int i=0;i<n_in&&i<32&&nc<2;i++) if(!used[i]){cand[nc++]=(const float*)d_in[i];used[i]=1;}
        if (nc<2 || in_sizes[imax]==in_sizes[iw] || in_sizes[iw]<=in_sizes[imin]){
            gin=(const float*)d_in[0]; cand[0]=(const float*)d_in[1]; cand[1]=(const float*)d_in[2];
            gfcw=(const float*)d_in[3]; gfcb=(const float*)d_in[4];
        }
    }
    cudaFuncSetAttribute(netvlad_kernel, cudaFuncAttributeMaxDynamicSharedMemorySize, SMEM_TOTAL);
    netvlad_kernel<<<Bb, NT, SMEM_TOTAL>>>(gin, cand[0], cand[1], gfcw, gfcb, (float*)d_out);
}

// round 13
// speedup vs baseline: 1.7854x; 1.7854x over previous
#include <cuda_runtime.h>
#include <cuda_bf16.h>

#define Bb 256
#define Tt 240
#define Cc 512
#define Kk 64
#define NCn 4
#define TB 16
#define NCHUNK 15
#define NT 1024
#define XS 516            // raw x row stride (f32)
#define CPB 520           // conv bf16 row stride
#define AS 68             // a_s row stride (f32)
#define VS 513            // vlad row stride

// smem byte offsets
#define CONV_OFF 0                 // bf16 [64][520] = 66560
#define XRAW_OFF 66560             // f32 [2][16][516] = 66048 -> 132608
#define RED_OFF  132608            // f32 [4][16][65] = 16640 -> 149248
#define A_OFF    149248            // f32 [16][68] = 4352 -> 153600
#define ASUM_OFF 153600
#define KN_OFF   153856
#define MISC_OFF 154112
#define WRED_OFF 154176
#define SMEM_TOTAL 154240

typedef unsigned int uint;

__device__ __forceinline__ void cp_async16(void* d,const void* s){uint a=(uint)__cvta_generic_to_shared(d);asm volatile("cp.async.cg.shared.global [%0],[%1],16;"::"r"(a),"l"(s));}
// pack {lo=x0, hi=x1} bf16x2
__device__ __forceinline__ uint bfp(float x0,float x1){uint r;asm("cvt.rn.bf16x2.f32 %0,%1,%2;":"=r"(r):"f"(x1),"f"(x0));return r;}
__device__ __forceinline__ void mma16(float* c,uint a0,uint a1,uint a2,uint a3,uint b0,uint b1){
    asm("mma.sync.aligned.m16n8k16.row.col.f32.bf16.bf16.f32 {%0,%1,%2,%3},{%4,%5,%6,%7},{%8,%9},{%0,%1,%2,%3};"
        : "+f"(c[0]),"+f"(c[1]),"+f"(c[2]),"+f"(c[3])
        : "r"(a0),"r"(a1),"r"(a2),"r"(a3),"r"(b0),"r"(b1));}

__global__ void __launch_bounds__(NT,1)
netvlad_kernel(const float* __restrict__ gin, const float* __restrict__ candA,
               const float* __restrict__ candB, const float* __restrict__ gfcw,
               const float* __restrict__ gfcb, float* __restrict__ gout)
{
    extern __shared__ __align__(1024) char smraw[];
    __nv_bfloat16* convb=(__nv_bfloat16*)(smraw+CONV_OFF);
    float* red  =(float*)(smraw+RED_OFF);
    float* a_s  =(float*)(smraw+A_OFF);
    float* asum_s=(float*)(smraw+ASUM_OFF);
    float* knorm=(float*)(smraw+KN_OFF);
    float* misc =(float*)(smraw+MISC_OFF);
    float* wred =(float*)(smraw+WRED_OFF);
    const int tid=threadIdx.x, lane=tid&31, warp=tid>>5, b=blockIdx.x;

    if (warp==0){
        float s=fabsf(candA[lane])+fabsf(candA[lane+32])+fabsf(candA[lane+64])+fabsf(candA[lane+96]);
        #pragma unroll
        for(int o=16;o;o>>=1) s+=__shfl_xor_sync(0xffffffffu,s,o);
        if(lane==0) misc[7]=s;
    }
    if (tid<Kk){asum_s[tid]=0.f; knorm[tid]=0.f;}
    if (tid<8) wred[tid]=0.f;
    __syncthreads();
    const bool aIsConv=(misc[7]<25.6f);
    const float* gconv=aIsConv?candA:candB;
    const float* gcent=aIsConv?candB:candA;
    __syncthreads();

    // conv f32 -> bf16 smem [64][520]
    for(int idx=tid;idx<Kk*Cc;idx+=NT){int k=idx>>9,c=idx&511;convb[k*CPB+c]=__float2bfloat16(gconv[idx]);}

    const float* inb=gin+(size_t)b*(Tt*Cc);
    {   // chunk 0 raw -> buf0 (16 rows x 512)
        int row=tid>>6, col=(tid&63)*8;
        float* d=(float*)(smraw+XRAW_OFF)+row*XS+col;
        const float* s=inb+row*Cc+col;
        *(float4*)d=*(const float4*)s; *(float4*)(d+4)=*(const float4*)(s+4);
    }

    // frag ids
    const int grp=lane>>2, tig=lane&3;
    const int kt=warp>>3, cg=warp&7;       // VLAD mma roles (also phase2: ks=kt, nt=cg)
    float acc[8][4];
    #pragma unroll
    for(int i=0;i<8;i++){acc[i][0]=0.f;acc[i][1]=0.f;acc[i][2]=0.f;acc[i][3]=0.f;}
    __syncthreads();

    for (int ch=0; ch<NCHUNK; ch++){
        float* xb=(float*)(smraw+XRAW_OFF)+(ch&1)*(TB*XS);
        if (ch+1<NCHUNK){
            int row=tid>>6, col=(tid&63)*8;
            float* d=(float*)(smraw+XRAW_OFF)+((ch+1)&1)*(TB*XS)+row*XS+col;
            const float* s=inb+(ch+1)*(TB*Cc)+row*Cc+col;
            cp_async16(d,s); cp_async16(d+4,s+4);
            asm volatile("cp.async.commit_group;");
        }
        // ---- phase 2: logits via HMMA. warp=(ks=kt, nt=cg): 128-c slice x 8 k_cl ----
        {
            float pacc[4]={0.f,0.f,0.f,0.f};
            const int kcl=cg*8+grp;
            const __nv_bfloat16* brow=convb+kcl*CPB+kt*128;
            #pragma unroll
            for(int s=0;s<8;s++){
                int c0=kt*128+s*16+2*tig;
                uint a0=bfp(xb[grp*XS+c0],     xb[grp*XS+c0+1]);
                uint a1=bfp(xb[(grp+8)*XS+c0], xb[(grp+8)*XS+c0+1]);
                uint a2=bfp(xb[grp*XS+c0+8],   xb[grp*XS+c0+9]);
                uint a3=bfp(xb[(grp+8)*XS+c0+8],xb[(grp+8)*XS+c0+9]);
                uint b0=*(const uint*)(brow+s*16+2*tig);
                uint b1=*(const uint*)(brow+s*16+2*tig+8);
                mma16(pacc,a0,a1,a2,a3,b0,b1);
            }
            // pacc: {t=grp,k=2tig},{t=grp,k=2tig+1},{t=grp+8,...}
            int ko=cg*8+2*tig;
            red[kt*1040+grp*65+ko]      =pacc[0];
            red[kt*1040+grp*65+ko+1]    =pacc[1];
            red[kt*1040+(grp+8)*65+ko]  =pacc[2];
            red[kt*1040+(grp+8)*65+ko+1]=pacc[3];
        }
        __syncthreads();   // B1
        // ---- softmax + norm scaling (warps 0..15, t=warp) ----
        if (warp<16){
            const int t=warp;
            const float* rp=xb+t*XS+4*lane;
            float4 q0=*(const float4*)rp,q1=*(const float4*)(rp+128),q2=*(const float4*)(rp+256),q3=*(const float4*)(rp+384);
            float ss=q0.x*q0.x+q0.y*q0.y+q0.z*q0.z+q0.w*q0.w+q1.x*q1.x+q1.y*q1.y+q1.z*q1.z+q1.w*q1.w
                    +q2.x*q2.x+q2.y*q2.y+q2.z*q2.z+q2.w*q2.w+q3.x*q3.x+q3.y*q3.y+q3.z*q3.z+q3.w*q3.w;
            #pragma unroll
            for(int o=16;o;o>>=1) ss+=__shfl_xor_sync(0xffffffffu,ss,o);
            float inv=1.0f/fmaxf(sqrtf(ss),1e-12f);
            float lg0=0.f,lg1=0.f;
            #pragma unroll
            for(int s=0;s<4;s++){lg0+=red[s*1040+t*65+lane];lg1+=red[s*1040+t*65+lane+32];}
            lg0*=inv; lg1*=inv;
            float m=fmaxf(lg0,lg1);
            #pragma unroll
            for(int o=16;o;o>>=1) m=fmaxf(m,__shfl_xor_sync(0xffffffffu,m,o));
            float e0=__expf(lg0-m),e1=__expf(lg1-m),s2=e0+e1;
            #pragma unroll
            for(int o=16;o;o>>=1) s2+=__shfl_xor_sync(0xffffffffu,s2,o);
            float a0=e0/s2,a1=e1/s2;
            a_s[t*AS+lane]=a0*inv; a_s[t*AS+lane+32]=a1*inv;  // a' = a/||x||
            atomicAdd(&asum_s[lane],a0); atomicAdd(&asum_s[lane+32],a1);
        }
        __syncthreads();   // B2
        // ---- VLAD mma: agg[64k,512c] += a'^T @ x_raw, k16 over t ----
        {
            const int r=kt*16+grp;
            uint fa0=bfp(a_s[(2*tig)*AS+r],   a_s[(2*tig+1)*AS+r]);
            uint fa1=bfp(a_s[(2*tig)*AS+r+8], a_s[(2*tig+1)*AS+r+8]);
            uint fa2=bfp(a_s[(2*tig+8)*AS+r],   a_s[(2*tig+9)*AS+r]);
            uint fa3=bfp(a_s[(2*tig+8)*AS+r+8], a_s[(2*tig+9)*AS+r+8]);
            const int cb=cg*64+grp;
            #pragma unroll
            for(int i=0;i<8;i++){
                int c=cb+i*8;
                uint fb0=bfp(xb[(2*tig)*XS+c],   xb[(2*tig+1)*XS+c]);
                uint fb1=bfp(xb[(2*tig+8)*XS+c], xb[(2*tig+9)*XS+c]);
                mma16(acc[i],fa0,fa1,fa2,fa3,fb0,fb1);
            }
        }
        if (ch+1<NCHUNK) asm volatile("cp.async.wait_group 0;");
        __syncthreads();   // B3
    }

    // ===== epilogue (R12-verified) =====
    float* vlad=(float*)smraw;   // overlay conv+xraw, stride VS
    {
        int r0=kt*16+grp, r1=r0+8;
        float a0s=asum_s[r0], a1s=asum_s[r1];
        float pk0=0.f, pk1=0.f;
        #pragma unroll
        for(int i=0;i<8;i++){
            int c=cg*64+i*8+2*tig;
            float2 c0=*(const float2*)(gcent+(size_t)r0*Cc+c);
            float2 c1=*(const float2*)(gcent+(size_t)r1*Cc+c);
            float v00=acc[i][0]-a0s*c0.x, v01=acc[i][1]-a0s*c0.y;
            float v10=acc[i][2]-a1s*c1.x, v11=acc[i][3]-a1s*c1.y;
            vlad[r0*VS+c]=v00; vlad[r0*VS+c+1]=v01;
            vlad[r1*VS+c]=v10; vlad[r1*VS+c+1]=v11;
            pk0+=v00*v00+v01*v01; pk1+=v10*v10+v11*v11;
        }
        pk0+=__shfl_xor_sync(0xffffffffu,pk0,1); pk0+=__shfl_xor_sync(0xffffffffu,pk0,2);
        pk1+=__shfl_xor_sync(0xffffffffu,pk1,1); pk1+=__shfl_xor_sync(0xffffffffu,pk1,2);
        if(tig==0){atomicAdd(&knorm[r0],pk0); atomicAdd(&knorm[r1],pk1);}
    }
    __syncthreads();
    if (warp==0){
        float c0=0.f;
        #pragma unroll
        for(int r=0;r<2;r++){float nn=knorm[lane+32*r];float iv=1.0f/fmaxf(sqrtf(nn),1e-12f);c0+=nn*iv*iv;}
        #pragma unroll
        for(int o=16;o;o>>=1) c0+=__shfl_xor_sync(0xffffffffu,c0,o);
        if(lane==0) misc[0]=1.0f/fmaxf(sqrtf(c0),1e-12f);
    }
    __syncthreads();
    {
        float invtot=misc[0];
        int k=tid>>4;
        float sc=(1.0f/fmaxf(sqrtf(knorm[k]),1e-12f))*invtot;
        int off=(tid&15)*32;
        float fo[NCn]={0.f,0.f,0.f,0.f};
        #pragma unroll 4
        for(int o=0;o<32;o++){
            int j=off+((o+lane)&31);
            float v=vlad[k*VS+j]*sc;
            #pragma unroll
            for(int n=0;n<NCn;n++) fo[n]+=v*gfcw[(size_t)n*(Kk*Cc)+k*Cc+j];
        }
        #pragma unroll
        for(int n=0;n<NCn;n++){
            float v=fo[n];
            #pragma unroll
            for(int o=16;o;o>>=1) v+=__shfl_xor_sync(0xffffffffu,v,o);
            if(lane==0) atomicAdd(&wred[n],v);
        }
    }
    __syncthreads();
    if (tid<NCn){
        float z=gfcb[tid]+wred[tid];
        gout[b*NCn+tid]=1.0f/(1.0f+__expf(-z));
    }
}

extern "C" void kernel_launch(void* const* d_in, const int* in_sizes, int n_in,
                              void* d_out, int out_size) {
    const float *gin=nullptr,*gfcw=nullptr,*gfcb=nullptr,*cand[2]={nullptr,nullptr};
    if (n_in>=5){
        int used[32]; for(int i=0;i<n_in&&i<32;i++) used[i]=0;
        int imax=-1; for(int i=0;i<n_in&&i<32;i++) if(!used[i]&&(imax<0||in_sizes[i]>in_sizes[imax])) imax=i;
        used[imax]=1; gin=(const float*)d_in[imax];
        int imin=-1; for(int i=0;i<n_in&&i<32;i++) if(!used[i]&&(imin<0||in_sizes[i]<in_sizes[imin])) imin=i;
        used[imin]=1; gfcb=(const float*)d_in[imin];
        int iw=-1; for(int i=0;i<n_in&&i<32;i++) if(!used[i]&&(iw<0||in_sizes[i]>in_sizes[iw])) iw=i;
        used[iw]=1; gfcw=(const float*)d_in[iw];
        int nc=0; for(int i=0;i<n_in&&i<32&&nc<2;i++) if(!used[i]){cand[nc++]=(const float*)d_in[i];used[i]=1;}
        if (nc<2 || in_sizes[imax]==in_sizes[iw] || in_sizes[iw]<=in_sizes[imin]){
            gin=(const float*)d_in[0]; cand[0]=(const float*)d_in[1]; cand[1]=(const float*)d_in[2];
            gfcw=(const float*)d_in[3]; gfcb=(const float*)d_in[4];
        }
    }
    cudaFuncSetAttribute(netvlad_kernel, cudaFuncAttributeMaxDynamicSharedMemorySize, SMEM_TOTAL);
    netvlad_kernel<<<Bb, NT, SMEM_TOTAL>>>(gin, cand[0], cand[1], gfcw, gfcb, (float*)d_out);
}